// round 15
// baseline (speedup 1.0000x reference)
#include <cuda_runtime.h>

#define L 64
#define C 7
#define NSTEPS 126   // (L-1)*K, K=2, h=0.5
#define NBPAIR 7     // batches per warp-pair
#define NCTA 293     // 2 pairs per CTA

typedef unsigned long long ull;

__device__ __forceinline__ ull ffma2(ull a, ull b, ull c) {
    ull d;
    asm("fma.rn.f32x2 %0, %1, %2, %3;" : "=l"(d) : "l"(a), "l"(b), "l"(c));
    return d;
}
__device__ __forceinline__ ull pk2(float x, float y) {
    ull r;
    asm("mov.b64 %0, {%1, %2};" : "=l"(r) : "f"(x), "f"(y));
    return r;
}
__device__ __forceinline__ void upk2(ull v, float &x, float &y) {
    asm("mov.b64 {%0, %1}, %2;" : "=f"(x), "=f"(y) : "l"(v));
}
__device__ __forceinline__ float sp_(float x) {
    return fmaxf(x, 0.f) + __logf(1.f + __expf(-fabsf(x)));
}
__device__ __forceinline__ float tanh_(float x) {
    float y;
    asm("tanh.approx.f32 %0, %1;" : "=f"(y) : "f"(x));
    return y;
}

#define BAR_ARRIVE(id) asm volatile("bar.arrive %0, 64;" :: "r"(id) : "memory")
#define BAR_SYNCN(id)  asm volatile("bar.sync %0, 64;"   :: "r"(id) : "memory")

// mm1 for NB batches starting at row sZb (stride 32), h1 -> sH1b
template<int NB>
__device__ __forceinline__ void mm1_run(const float* sZb, const ull* rw1, float rbf1,
                                        float* sH1b, int lane) {
    ull a1[NB];
#pragma unroll
    for (int k = 0; k < NB; k++) a1[k] = 0ull;
#pragma unroll
    for (int q = 0; q < 8; q++) {
#pragma unroll
        for (int k = 0; k < NB; k++) {
            ulonglong2 zq = *reinterpret_cast<const ulonglong2*>(sZb + k * 32 + 4 * q);
            a1[k] = ffma2(zq.x, rw1[2 * q], a1[k]);
            a1[k] = ffma2(zq.y, rw1[2 * q + 1], a1[k]);
        }
    }
#pragma unroll
    for (int k = 0; k < NB; k++) {
        float u, v; upk2(a1[k], u, v);
        sH1b[k * 32 + lane] = sp_(u + v + rbf1);
    }
}

// mm2 + tanh + einsum partial for TWO batches (NCH own channels)
template<int NCH>
__device__ __forceinline__ void mm2_two(const float* h0, const float* h1,
                                        const float* d0, const float* d1,
                                        const ull (*wreg)[16], const float* b2,
                                        float& r0, float& r1) {
    ull a0[NCH], a1[NCH];
#pragma unroll
    for (int c = 0; c < NCH; c++) { a0[c] = 0ull; a1[c] = 0ull; }
#pragma unroll
    for (int q = 0; q < 8; q++) {
        ulonglong2 hq0 = *reinterpret_cast<const ulonglong2*>(h0 + 4 * q);
        ulonglong2 hq1 = *reinterpret_cast<const ulonglong2*>(h1 + 4 * q);
#pragma unroll
        for (int c = 0; c < NCH; c++) {
            a0[c] = ffma2(hq0.x, wreg[c][2 * q], a0[c]);
            a1[c] = ffma2(hq1.x, wreg[c][2 * q], a1[c]);
            a0[c] = ffma2(hq0.y, wreg[c][2 * q + 1], a0[c]);
            a1[c] = ffma2(hq1.y, wreg[c][2 * q + 1], a1[c]);
        }
    }
    float g0[NCH], g1[NCH];
#pragma unroll
    for (int c = 0; c < NCH; c++) {
        float u, v;
        upk2(a0[c], u, v); g0[c] = tanh_(u + v + b2[c]);
        upk2(a1[c], u, v); g1[c] = tanh_(u + v + b2[c]);
    }
    ull e0 = ffma2(pk2(g0[0], g0[1]), *reinterpret_cast<const ull*>(d0), 0ull);
    ull e1 = ffma2(pk2(g1[0], g1[1]), *reinterpret_cast<const ull*>(d1), 0ull);
    if (NCH == 4) {
        e0 = ffma2(pk2(g0[2], g0[3]), *reinterpret_cast<const ull*>(d0 + 2), e0);
        e1 = ffma2(pk2(g1[2], g1[3]), *reinterpret_cast<const ull*>(d1 + 2), e1);
    }
    float a, b;
    upk2(e0, a, b); r0 = a + b;
    upk2(e1, a, b); r1 = a + b;
    if (NCH == 3) {
        r0 = fmaf(g0[2], d0[2], r0);
        r1 = fmaf(g1[2], d1[2], r1);
    }
}

// single-batch variant
template<int NCH>
__device__ __forceinline__ float mm2_one(const float* h0, const float* d0,
                                         const ull (*wreg)[16], const float* b2) {
    ull a0[NCH];
#pragma unroll
    for (int c = 0; c < NCH; c++) a0[c] = 0ull;
#pragma unroll
    for (int q = 0; q < 8; q++) {
        ulonglong2 hq0 = *reinterpret_cast<const ulonglong2*>(h0 + 4 * q);
#pragma unroll
        for (int c = 0; c < NCH; c++) {
            a0[c] = ffma2(hq0.x, wreg[c][2 * q], a0[c]);
            a0[c] = ffma2(hq0.y, wreg[c][2 * q + 1], a0[c]);
        }
    }
    float g0[NCH];
#pragma unroll
    for (int c = 0; c < NCH; c++) {
        float u, v; upk2(a0[c], u, v);
        g0[c] = tanh_(u + v + b2[c]);
    }
    ull e0 = ffma2(pk2(g0[0], g0[1]), *reinterpret_cast<const ull*>(d0), 0ull);
    if (NCH == 4) e0 = ffma2(pk2(g0[2], g0[3]), *reinterpret_cast<const ull*>(d0 + 2), e0);
    float a, b; upk2(e0, a, b);
    float r = a + b;
    if (NCH == 3) r = fmaf(g0[2], d0[2], r);
    return r;
}

__global__ __launch_bounds__(128, 2)
void cde_kernel(const float* __restrict__ X,      // (4096,64,7)
                const float* __restrict__ Winit,  // (32,7)
                const float* __restrict__ binit,  // (32)
                const float* __restrict__ Wf1,    // (32,32)
                const float* __restrict__ bf1,    // (32)
                const float* __restrict__ Wf2,    // (224,32)
                const float* __restrict__ bf2,    // (224)
                const float* __restrict__ Wo1,    // (16,32)
                const float* __restrict__ bo1,    // (16)
                const float* __restrict__ Wo2,    // (3,16)
                const float* __restrict__ bo2,    // (3)
                float* __restrict__ out)          // (4096,3)
{
    // 4 warps = 2 pairs; pair serves 7 batches.
    // Warp A (isB=0): channels {0..3} (NCH=4), batches {0,1}   (nb=2)
    // Warp B (isB=1): channels {4,5,6} (NCH=3), batches {2..6} (nb=5)
    __shared__ __align__(16) float sZ[2][8][32];      // zs per batch slot (owner-written)
    __shared__ __align__(16) float sH1[2][8][32];     // h1 (owner-written)
    __shared__ __align__(16) float sDX[2][3][8][8];   // spline values
    __shared__ __align__(16) float sPartX[2][8][32];  // partner-written einsum partials

    const int tid  = threadIdx.x;
    const int w    = tid >> 5;
    const int lane = tid & 31;          // = h
    const int pair = w >> 1;
    const int isB  = w & 1;
    const int gpair = blockIdx.x * 2 + pair;
    const int pairbase = gpair * NBPAIR;

    const int b0  = isB ? 2 : 0;
    const int nb  = isB ? 5 : 2;
    const int c0  = isB ? 4 : 0;        // first owned channel
    const int nch = isB ? 3 : 4;
    // named barriers (count 64 = 32 arrive + 32 sync):
    //  b1: B h1 chunk {2,3,4} -> A     b2: B h1 chunk {5,6} -> A
    //  b3: A h1 {0,1} -> B
    //  b4: B partials -> A             b5: A partials -> B
    const int base = pair * 5;

    // ---- Wf2 owned channels, j-pair packed, in registers ----
    ull wreg[4][16];
    float b2[4];
#pragma unroll
    for (int cp = 0; cp < 4; cp++) {
        if (cp < nch) {
            int cg = c0 + cp;
            const float2* wp = reinterpret_cast<const float2*>(Wf2 + (lane * C + cg) * 32);
#pragma unroll
            for (int jp = 0; jp < 16; jp++) { float2 v = __ldg(wp + jp); wreg[cp][jp] = pk2(v.x, v.y); }
            b2[cp] = __ldg(bf2 + lane * C + cg);
        } else {
#pragma unroll
            for (int jp = 0; jp < 16; jp++) wreg[cp][jp] = 0ull;
            b2[cp] = 0.f;
        }
    }
    ull rw1[16];
    {
        const float2* p1 = reinterpret_cast<const float2*>(Wf1 + lane * 32);
#pragma unroll
        for (int jp = 0; jp < 16; jp++) { float2 v = __ldg(p1 + jp); rw1[jp] = pk2(v.x, v.y); }
    }
    const float rbf1 = __ldg(bf1 + lane);

    // spline mapping: A writes dX rows 0-3, B rows 4-7 (row 7 dummy)
    const int db = lane >> 3;
    const int dc = lane & 7;
    const int srow = isB * 4 + db;
    const int sbatch = min(pairbase + srow, 4095);
    const float* xrow = X + (size_t)sbatch * (L * C) + ((dc < C) ? dc : 0);

    // z0 for own batches
    float z[5], ksum[5];
#pragma unroll
    for (int k = 0; k < 5; k++) { z[k] = 0.f; ksum[k] = 0.f; }
    for (int k = 0; k < nb; k++) {
        int gb = min(pairbase + b0 + k, 4095);
        float acc = __ldg(binit + lane);
        const float* xp = X + (size_t)gb * (L * C);
#pragma unroll
        for (int c = 0; c < C; c++) acc = fmaf(__ldg(xp + c), __ldg(Winit + lane * C + c), acc);
        z[k] = acc;
        sZ[pair][b0 + k][lane] = acc;
    }

    // initial dX(t=0) -> slot 0  (idx=0,f=0 -> diff)
    {
        float v = 0.f;
        if (dc < C) v = __ldg(xrow + C) - __ldg(xrow);
        sDX[pair][0][srow][dc] = v;
    }
    __syncthreads();

    // stencil carry registers (updated on even i)
    float st_diff = 0.f, st_m0 = 0.f, st_dm = 0.f;

#pragma unroll 1
    for (int i = 0; i < NSTEPS; i++) {
        // ---- spline: stencil advances only on even i; m1 == diff algebraically ----
        {
            if (!(i & 1)) {
                const int m = i >> 1;
                const float* p = xrow + m * C;
                float xm1 = 0.f, x0 = 0.f, x1 = 0.f;
                if (dc < C) {
                    x0 = __ldg(p);
                    x1 = __ldg(p + C);
                    if (m > 0) xm1 = __ldg(p - C);
                }
                st_diff = x1 - x0;
                st_m0 = (m > 0) ? (x0 - xm1) : st_diff;
                st_dm = st_diff - st_m0;
            }
            // eval(f) = m0 + dm * f * (4 - 3f);  f=0.25->0.8125, 0.5->1.25, 0.75->1.3125
            float fac = (i & 1) ? 1.3125f : 0.8125f;
            float vb = fmaf(st_dm, fac, st_m0);
            float vc = (i & 1) ? st_diff : fmaf(st_dm, 1.25f, st_m0);
            sDX[pair][2][srow][dc] = vb;
            sDX[pair][(i + 1) & 1][srow][dc] = vc;
        }
        const int slotA = i & 1, slotC = (i + 1) & 1;

#pragma unroll 1
        for (int s = 0; s < 4; s++) {
            const int slot = (s == 0) ? slotA : ((s == 3) ? slotC : 2);
            const float* dxs = &sDX[pair][slot][0][0];   // rows of 8
            float* sPx = &sPartX[pair][0][0];
            const float* h1t = &sH1[pair][0][0];

            __syncwarp();
            const float wk = (s == 1 || s == 2) ? 2.f : 1.f;
            const float an = (s < 2) ? 0.25f : 0.5f;

            if (!isB) {
                // ---- A: mm1 {0,1} -> publish -> mm2 own (regs) -> consume B chunks ----
                mm1_run<2>(&sZ[pair][0][0], rw1, rbf1, &sH1[pair][0][0], lane);
                BAR_ARRIVE(base + 3);
                float own0, own1;
                mm2_two<4>(h1t, h1t + 32, dxs, dxs + 8, wreg, b2, own0, own1);
                BAR_SYNCN(base + 1);          // B h1 {2,3,4} ready
                {
                    float r0, r1;
                    mm2_two<4>(h1t + 64, h1t + 96, dxs + 16, dxs + 24, wreg, b2, r0, r1);
                    sPx[64 + lane] = r0; sPx[96 + lane] = r1;
                    sPx[128 + lane] = mm2_one<4>(h1t + 128, dxs + 32, wreg, b2);
                }
                BAR_SYNCN(base + 2);          // B h1 {5,6} ready
                {
                    float r0, r1;
                    mm2_two<4>(h1t + 160, h1t + 192, dxs + 40, dxs + 48, wreg, b2, r0, r1);
                    sPx[160 + lane] = r0; sPx[192 + lane] = r1;
                }
                BAR_ARRIVE(base + 5);         // my partials (rows 2-6) -> B
                BAR_SYNCN(base + 4);          // B partials (rows 0-1) -> me

                // combine + RK4 for batches {0,1}
                float kk0 = own0 + sPx[lane];
                float kk1 = own1 + sPx[32 + lane];
                ksum[0] = fmaf(wk, kk0, ksum[0]);
                ksum[1] = fmaf(wk, kk1, ksum[1]);
                float z0v, z1v;
                if (s < 3) {
                    z0v = fmaf(an, kk0, z[0]);
                    z1v = fmaf(an, kk1, z[1]);
                } else {
                    z[0] = fmaf(ksum[0], (1.f / 12.f), z[0]); ksum[0] = 0.f; z0v = z[0];
                    z[1] = fmaf(ksum[1], (1.f / 12.f), z[1]); ksum[1] = 0.f; z1v = z[1];
                }
                sZ[pair][0][lane] = z0v;
                sZ[pair][1][lane] = z1v;
            } else {
                // ---- B (REORDERED): mm1 chunks -> partner-mm2 EARLY -> own-mm2 ----
                mm1_run<3>(&sZ[pair][2][0], rw1, rbf1, &sH1[pair][2][0], lane);
                BAR_ARRIVE(base + 1);
                mm1_run<2>(&sZ[pair][5][0], rw1, rbf1, &sH1[pair][5][0], lane);
                BAR_ARRIVE(base + 2);
                BAR_SYNCN(base + 3);          // A h1 {0,1} ready (A arrived early)
                {   // partner-mm2 FIRST: unblocks A's combine asap
                    float r0, r1;
                    mm2_two<3>(h1t, h1t + 32, dxs + 4, dxs + 8 + 4, wreg, b2, r0, r1);
                    sPx[lane] = r0; sPx[32 + lane] = r1;
                }
                BAR_ARRIVE(base + 4);         // my partials (rows 0-1) -> A (EARLY)
                float ownp[5];
                {   // own-mm2 batches {2..6}, channels {4,5,6} (results stay in regs)
                    mm2_two<3>(h1t + 64, h1t + 96, dxs + 16 + 4, dxs + 24 + 4, wreg, b2, ownp[0], ownp[1]);
                    mm2_two<3>(h1t + 128, h1t + 160, dxs + 32 + 4, dxs + 40 + 4, wreg, b2, ownp[2], ownp[3]);
                    ownp[4] = mm2_one<3>(h1t + 192, dxs + 48 + 4, wreg, b2);
                }
                BAR_SYNCN(base + 5);          // A partials (rows 2-6) -> me

                // combine + RK4 for batches {2..6}
#pragma unroll
                for (int k = 0; k < 5; k++) {
                    int bs = 2 + k;
                    float kk = ownp[k] + sPx[bs * 32 + lane];
                    ksum[k] = fmaf(wk, kk, ksum[k]);
                    float zsv;
                    if (s < 3) {
                        zsv = fmaf(an, kk, z[k]);
                    } else {
                        z[k] = fmaf(ksum[k], (1.f / 12.f), z[k]);
                        ksum[k] = 0.f;
                        zsv = z[k];
                    }
                    sZ[pair][bs][lane] = zsv;
                }
            }
        }
    }

    __syncthreads();   // drain before scratch reuse

    // ---- output head (own batches) ----
    __syncwarp();
    // disjoint scratch: A rows 0-1, B rows 2-6 of sPartX[pair]
    float* so = &sPartX[pair][b0][0];
    if (lane < 16) {
        for (int k = 0; k < nb; k++) {
            float acc = __ldg(bo1 + lane);
#pragma unroll
            for (int hh = 0; hh < 32; hh++)
                acc = fmaf(sZ[pair][b0 + k][hh], __ldg(Wo1 + lane * 32 + hh), acc);
            so[k * 32 + lane] = sp_(acc);
        }
    }
    __syncwarp();
    if (lane < 3 * nb) {
        int k = lane / 3;
        int jo = lane - 3 * k;
        int gb = pairbase + b0 + k;
        if (gb < 4096) {
            float acc = __ldg(bo2 + jo);
#pragma unroll
            for (int i2 = 0; i2 < 16; i2++)
                acc = fmaf(so[k * 32 + i2], __ldg(Wo2 + jo * 16 + i2), acc);
            out[(size_t)gb * 3 + jo] = acc;
        }
    }
}

extern "C" void kernel_launch(void* const* d_in, const int* in_sizes, int n_in,
                              void* d_out, int out_size) {
    const float* X     = (const float*)d_in[0];
    const float* Winit = (const float*)d_in[1];
    const float* binit = (const float*)d_in[2];
    const float* Wf1   = (const float*)d_in[3];
    const float* bf1   = (const float*)d_in[4];
    const float* Wf2   = (const float*)d_in[5];
    const float* bf2   = (const float*)d_in[6];
    const float* Wo1   = (const float*)d_in[7];
    const float* bo1   = (const float*)d_in[8];
    const float* Wo2   = (const float*)d_in[9];
    const float* bo2   = (const float*)d_in[10];
    float* out = (float*)d_out;

    // 293 CTAs x 128 thr: 2 pairs/CTA x 7 batches = 4102 slots >= 4096 (tail guarded)
    cde_kernel<<<NCTA, 128>>>(X, Winit, binit, Wf1, bf1, Wf2, bf2,
                              Wo1, bo1, Wo2, bo2, out);
}

// round 16
// speedup vs baseline: 1.0205x; 1.0205x over previous
#include <cuda_runtime.h>

#define L 64
#define C 7
#define NSTEPS 126   // (L-1)*K, K=2, h=0.5
#define NBPAIR 7     // batches per warp-pair
#define NCTA 293     // 2 pairs per CTA

typedef unsigned long long ull;

__device__ __forceinline__ ull ffma2(ull a, ull b, ull c) {
    ull d;
    asm("fma.rn.f32x2 %0, %1, %2, %3;" : "=l"(d) : "l"(a), "l"(b), "l"(c));
    return d;
}
__device__ __forceinline__ ull pk2(float x, float y) {
    ull r;
    asm("mov.b64 %0, {%1, %2};" : "=l"(r) : "f"(x), "f"(y));
    return r;
}
__device__ __forceinline__ void upk2(ull v, float &x, float &y) {
    asm("mov.b64 {%0, %1}, %2;" : "=f"(x), "=f"(y) : "l"(v));
}
__device__ __forceinline__ float sp_(float x) {
    return fmaxf(x, 0.f) + __logf(1.f + __expf(-fabsf(x)));
}
__device__ __forceinline__ float tanh_(float x) {
    float y;
    asm("tanh.approx.f32 %0, %1;" : "=f"(y) : "f"(x));
    return y;
}

#define BAR_ARRIVE(id) asm volatile("bar.arrive %0, 64;" :: "r"(id) : "memory")
#define BAR_SYNCN(id)  asm volatile("bar.sync %0, 64;"   :: "r"(id) : "memory")

// mm1 for NB batches starting at row sZb (stride 32), h1 -> sH1b
template<int NB>
__device__ __forceinline__ void mm1_run(const float* sZb, const ull* rw1, float rbf1,
                                        float* sH1b, int lane) {
    ull a1[NB];
#pragma unroll
    for (int k = 0; k < NB; k++) a1[k] = 0ull;
#pragma unroll
    for (int q = 0; q < 8; q++) {
#pragma unroll
        for (int k = 0; k < NB; k++) {
            ulonglong2 zq = *reinterpret_cast<const ulonglong2*>(sZb + k * 32 + 4 * q);
            a1[k] = ffma2(zq.x, rw1[2 * q], a1[k]);
            a1[k] = ffma2(zq.y, rw1[2 * q + 1], a1[k]);
        }
    }
#pragma unroll
    for (int k = 0; k < NB; k++) {
        float u, v; upk2(a1[k], u, v);
        sH1b[k * 32 + lane] = sp_(u + v + rbf1);
    }
}

// mm2 + tanh + einsum partial for TWO batches (NCH own channels)
template<int NCH>
__device__ __forceinline__ void mm2_two(const float* h0, const float* h1,
                                        const float* d0, const float* d1,
                                        const ull (*wreg)[16], const float* b2,
                                        float& r0, float& r1) {
    ull a0[NCH], a1[NCH];
#pragma unroll
    for (int c = 0; c < NCH; c++) { a0[c] = 0ull; a1[c] = 0ull; }
#pragma unroll
    for (int q = 0; q < 8; q++) {
        ulonglong2 hq0 = *reinterpret_cast<const ulonglong2*>(h0 + 4 * q);
        ulonglong2 hq1 = *reinterpret_cast<const ulonglong2*>(h1 + 4 * q);
#pragma unroll
        for (int c = 0; c < NCH; c++) {
            a0[c] = ffma2(hq0.x, wreg[c][2 * q], a0[c]);
            a1[c] = ffma2(hq1.x, wreg[c][2 * q], a1[c]);
            a0[c] = ffma2(hq0.y, wreg[c][2 * q + 1], a0[c]);
            a1[c] = ffma2(hq1.y, wreg[c][2 * q + 1], a1[c]);
        }
    }
    float g0[NCH], g1[NCH];
#pragma unroll
    for (int c = 0; c < NCH; c++) {
        float u, v;
        upk2(a0[c], u, v); g0[c] = tanh_(u + v + b2[c]);
        upk2(a1[c], u, v); g1[c] = tanh_(u + v + b2[c]);
    }
    ull e0 = ffma2(pk2(g0[0], g0[1]), *reinterpret_cast<const ull*>(d0), 0ull);
    ull e1 = ffma2(pk2(g1[0], g1[1]), *reinterpret_cast<const ull*>(d1), 0ull);
    if (NCH == 4) {
        e0 = ffma2(pk2(g0[2], g0[3]), *reinterpret_cast<const ull*>(d0 + 2), e0);
        e1 = ffma2(pk2(g1[2], g1[3]), *reinterpret_cast<const ull*>(d1 + 2), e1);
    }
    float a, b;
    upk2(e0, a, b); r0 = a + b;
    upk2(e1, a, b); r1 = a + b;
    if (NCH == 3) {
        r0 = fmaf(g0[2], d0[2], r0);
        r1 = fmaf(g1[2], d1[2], r1);
    }
}

// single-batch variant
template<int NCH>
__device__ __forceinline__ float mm2_one(const float* h0, const float* d0,
                                         const ull (*wreg)[16], const float* b2) {
    ull a0[NCH];
#pragma unroll
    for (int c = 0; c < NCH; c++) a0[c] = 0ull;
#pragma unroll
    for (int q = 0; q < 8; q++) {
        ulonglong2 hq0 = *reinterpret_cast<const ulonglong2*>(h0 + 4 * q);
#pragma unroll
        for (int c = 0; c < NCH; c++) {
            a0[c] = ffma2(hq0.x, wreg[c][2 * q], a0[c]);
            a0[c] = ffma2(hq0.y, wreg[c][2 * q + 1], a0[c]);
        }
    }
    float g0[NCH];
#pragma unroll
    for (int c = 0; c < NCH; c++) {
        float u, v; upk2(a0[c], u, v);
        g0[c] = tanh_(u + v + b2[c]);
    }
    ull e0 = ffma2(pk2(g0[0], g0[1]), *reinterpret_cast<const ull*>(d0), 0ull);
    if (NCH == 4) e0 = ffma2(pk2(g0[2], g0[3]), *reinterpret_cast<const ull*>(d0 + 2), e0);
    float a, b; upk2(e0, a, b);
    float r = a + b;
    if (NCH == 3) r = fmaf(g0[2], d0[2], r);
    return r;
}

__global__ __launch_bounds__(128, 2)
void cde_kernel(const float* __restrict__ X,      // (4096,64,7)
                const float* __restrict__ Winit,  // (32,7)
                const float* __restrict__ binit,  // (32)
                const float* __restrict__ Wf1,    // (32,32)
                const float* __restrict__ bf1,    // (32)
                const float* __restrict__ Wf2,    // (224,32)
                const float* __restrict__ bf2,    // (224)
                const float* __restrict__ Wo1,    // (16,32)
                const float* __restrict__ bo1,    // (16)
                const float* __restrict__ Wo2,    // (3,16)
                const float* __restrict__ bo2,    // (3)
                float* __restrict__ out)          // (4096,3)
{
    // 4 warps = 2 pairs; pair serves 7 batches.
    // Warp A (isB=0): channels {0..3} (NCH=4), batches {0,1}   (nb=2)
    // Warp B (isB=1): channels {4,5,6} (NCH=3), batches {2..6} (nb=5)
    __shared__ __align__(16) float sZ[2][8][32];      // zs per batch slot (owner-written)
    __shared__ __align__(16) float sH1[2][8][32];     // h1 (owner-written)
    __shared__ __align__(16) float sDX[2][3][8][8];   // spline values
    __shared__ __align__(16) float sPartX[2][8][32];  // partner-written einsum partials

    const int tid  = threadIdx.x;
    const int w    = tid >> 5;
    const int lane = tid & 31;          // = h
    const int pair = w >> 1;
    const int isB  = w & 1;
    const int gpair = blockIdx.x * 2 + pair;
    const int pairbase = gpair * NBPAIR;

    const int b0  = isB ? 2 : 0;
    const int nb  = isB ? 5 : 2;
    const int c0  = isB ? 4 : 0;        // first owned channel
    const int nch = isB ? 3 : 4;
    // named barriers (count 64 = 32 arrive + 32 sync):
    //  b1: B h1 chunk {2,3,4} -> A     b2: B h1 chunk {5,6} -> A
    //  b3: A h1 {0,1} -> B             b4: B partials (rows 0-1) -> A
    //  b5: A partials rows {2,3,4} -> B   b6: A partials rows {5,6} -> B
    const int base = pair * 6;

    // ---- Wf2 owned channels, j-pair packed, in registers ----
    ull wreg[4][16];
    float b2[4];
#pragma unroll
    for (int cp = 0; cp < 4; cp++) {
        if (cp < nch) {
            int cg = c0 + cp;
            const float2* wp = reinterpret_cast<const float2*>(Wf2 + (lane * C + cg) * 32);
#pragma unroll
            for (int jp = 0; jp < 16; jp++) { float2 v = __ldg(wp + jp); wreg[cp][jp] = pk2(v.x, v.y); }
            b2[cp] = __ldg(bf2 + lane * C + cg);
        } else {
#pragma unroll
            for (int jp = 0; jp < 16; jp++) wreg[cp][jp] = 0ull;
            b2[cp] = 0.f;
        }
    }
    ull rw1[16];
    {
        const float2* p1 = reinterpret_cast<const float2*>(Wf1 + lane * 32);
#pragma unroll
        for (int jp = 0; jp < 16; jp++) { float2 v = __ldg(p1 + jp); rw1[jp] = pk2(v.x, v.y); }
    }
    const float rbf1 = __ldg(bf1 + lane);

    // spline mapping: A writes dX rows 0-3, B rows 4-7 (row 7 dummy)
    const int db = lane >> 3;
    const int dc = lane & 7;
    const int srow = isB * 4 + db;
    const int sbatch = min(pairbase + srow, 4095);
    const float* xrow = X + (size_t)sbatch * (L * C) + ((dc < C) ? dc : 0);

    // z0 for own batches
    float z[5], ksum[5];
#pragma unroll
    for (int k = 0; k < 5; k++) { z[k] = 0.f; ksum[k] = 0.f; }
    for (int k = 0; k < nb; k++) {
        int gb = min(pairbase + b0 + k, 4095);
        float acc = __ldg(binit + lane);
        const float* xp = X + (size_t)gb * (L * C);
#pragma unroll
        for (int c = 0; c < C; c++) acc = fmaf(__ldg(xp + c), __ldg(Winit + lane * C + c), acc);
        z[k] = acc;
        sZ[pair][b0 + k][lane] = acc;
    }

    // initial dX(t=0) -> slot 0  (idx=0,f=0 -> diff)
    {
        float v = 0.f;
        if (dc < C) v = __ldg(xrow + C) - __ldg(xrow);
        sDX[pair][0][srow][dc] = v;
    }
    __syncthreads();

    // stencil carry registers (updated on even i)
    float st_diff = 0.f, st_m0 = 0.f, st_dm = 0.f;

#pragma unroll 1
    for (int i = 0; i < NSTEPS; i++) {
        // ---- spline: stencil advances only on even i; m1 == diff algebraically ----
        {
            if (!(i & 1)) {
                const int m = i >> 1;
                const float* p = xrow + m * C;
                float xm1 = 0.f, x0 = 0.f, x1 = 0.f;
                if (dc < C) {
                    x0 = __ldg(p);
                    x1 = __ldg(p + C);
                    if (m > 0) xm1 = __ldg(p - C);
                }
                st_diff = x1 - x0;
                st_m0 = (m > 0) ? (x0 - xm1) : st_diff;
                st_dm = st_diff - st_m0;
            }
            // eval(f) = m0 + dm * f * (4 - 3f);  f=0.25->0.8125, 0.5->1.25, 0.75->1.3125
            float fac = (i & 1) ? 1.3125f : 0.8125f;
            float vb = fmaf(st_dm, fac, st_m0);
            float vc = (i & 1) ? st_diff : fmaf(st_dm, 1.25f, st_m0);
            sDX[pair][2][srow][dc] = vb;
            sDX[pair][(i + 1) & 1][srow][dc] = vc;
        }
        const int slotA = i & 1, slotC = (i + 1) & 1;

#pragma unroll 1
        for (int s = 0; s < 4; s++) {
            const int slot = (s == 0) ? slotA : ((s == 3) ? slotC : 2);
            const float* dxs = &sDX[pair][slot][0][0];   // rows of 8
            float* sPx = &sPartX[pair][0][0];
            const float* h1t = &sH1[pair][0][0];

            __syncwarp();
            const float wk = (s == 1 || s == 2) ? 2.f : 1.f;
            const float an = (s < 2) ? 0.25f : 0.5f;

            if (!isB) {
                // ---- A: mm1 {0,1} -> publish -> mm2 own (regs) -> consume B chunks ----
                mm1_run<2>(&sZ[pair][0][0], rw1, rbf1, &sH1[pair][0][0], lane);
                BAR_ARRIVE(base + 3);
                float own0, own1;
                mm2_two<4>(h1t, h1t + 32, dxs, dxs + 8, wreg, b2, own0, own1);
                BAR_SYNCN(base + 1);          // B h1 {2,3,4} ready
                {
                    float r0, r1;
                    mm2_two<4>(h1t + 64, h1t + 96, dxs + 16, dxs + 24, wreg, b2, r0, r1);
                    sPx[64 + lane] = r0; sPx[96 + lane] = r1;
                    sPx[128 + lane] = mm2_one<4>(h1t + 128, dxs + 32, wreg, b2);
                }
                BAR_ARRIVE(base + 5);         // rows {2,3,4} -> B (EARLY)
                BAR_SYNCN(base + 2);          // B h1 {5,6} ready
                {
                    float r0, r1;
                    mm2_two<4>(h1t + 160, h1t + 192, dxs + 40, dxs + 48, wreg, b2, r0, r1);
                    sPx[160 + lane] = r0; sPx[192 + lane] = r1;
                }
                BAR_ARRIVE(base + 6);         // rows {5,6} -> B
                BAR_SYNCN(base + 4);          // B partials (rows 0-1) -> me

                // combine + RK4 for batches {0,1}
                float kk0 = own0 + sPx[lane];
                float kk1 = own1 + sPx[32 + lane];
                ksum[0] = fmaf(wk, kk0, ksum[0]);
                ksum[1] = fmaf(wk, kk1, ksum[1]);
                float z0v, z1v;
                if (s < 3) {
                    z0v = fmaf(an, kk0, z[0]);
                    z1v = fmaf(an, kk1, z[1]);
                } else {
                    z[0] = fmaf(ksum[0], (1.f / 12.f), z[0]); ksum[0] = 0.f; z0v = z[0];
                    z[1] = fmaf(ksum[1], (1.f / 12.f), z[1]); ksum[1] = 0.f; z1v = z[1];
                }
                sZ[pair][0][lane] = z0v;
                sZ[pair][1][lane] = z1v;
            } else {
                // ---- B: mm1 chunks -> own-mm2 -> partner-mm2 -> split combine ----
                mm1_run<3>(&sZ[pair][2][0], rw1, rbf1, &sH1[pair][2][0], lane);
                BAR_ARRIVE(base + 1);
                mm1_run<2>(&sZ[pair][5][0], rw1, rbf1, &sH1[pair][5][0], lane);
                BAR_ARRIVE(base + 2);
                float ownp[5];
                {   // mm2 own batches {2..6}, channels {4,5,6} (results stay in regs)
                    mm2_two<3>(h1t + 64, h1t + 96, dxs + 16 + 4, dxs + 24 + 4, wreg, b2, ownp[0], ownp[1]);
                    mm2_two<3>(h1t + 128, h1t + 160, dxs + 32 + 4, dxs + 40 + 4, wreg, b2, ownp[2], ownp[3]);
                    ownp[4] = mm2_one<3>(h1t + 192, dxs + 48 + 4, wreg, b2);
                }
                BAR_SYNCN(base + 3);          // A h1 {0,1} ready
                {
                    float r0, r1;
                    mm2_two<3>(h1t, h1t + 32, dxs + 4, dxs + 8 + 4, wreg, b2, r0, r1);
                    sPx[lane] = r0; sPx[32 + lane] = r1;
                }
                BAR_ARRIVE(base + 4);         // my partials (rows 0-1) -> A

                // combine batches {2,3,4} as soon as A's chunk1 lands
                BAR_SYNCN(base + 5);
#pragma unroll
                for (int k = 0; k < 3; k++) {
                    int bs = 2 + k;
                    float kk = ownp[k] + sPx[bs * 32 + lane];
                    ksum[k] = fmaf(wk, kk, ksum[k]);
                    float zsv;
                    if (s < 3) {
                        zsv = fmaf(an, kk, z[k]);
                    } else {
                        z[k] = fmaf(ksum[k], (1.f / 12.f), z[k]);
                        ksum[k] = 0.f;
                        zsv = z[k];
                    }
                    sZ[pair][bs][lane] = zsv;
                }
                // combine batches {5,6} after A's chunk2
                BAR_SYNCN(base + 6);
#pragma unroll
                for (int k = 3; k < 5; k++) {
                    int bs = 2 + k;
                    float kk = ownp[k] + sPx[bs * 32 + lane];
                    ksum[k] = fmaf(wk, kk, ksum[k]);
                    float zsv;
                    if (s < 3) {
                        zsv = fmaf(an, kk, z[k]);
                    } else {
                        z[k] = fmaf(ksum[k], (1.f / 12.f), z[k]);
                        ksum[k] = 0.f;
                        zsv = z[k];
                    }
                    sZ[pair][bs][lane] = zsv;
                }
            }
        }
    }

    __syncthreads();   // drain before scratch reuse

    // ---- output head (own batches) ----
    __syncwarp();
    // disjoint scratch: A rows 0-1, B rows 2-6 of sPartX[pair]
    float* so = &sPartX[pair][b0][0];
    if (lane < 16) {
        for (int k = 0; k < nb; k++) {
            float acc = __ldg(bo1 + lane);
#pragma unroll
            for (int hh = 0; hh < 32; hh++)
                acc = fmaf(sZ[pair][b0 + k][hh], __ldg(Wo1 + lane * 32 + hh), acc);
            so[k * 32 + lane] = sp_(acc);
        }
    }
    __syncwarp();
    if (lane < 3 * nb) {
        int k = lane / 3;
        int jo = lane - 3 * k;
        int gb = pairbase + b0 + k;
        if (gb < 4096) {
            float acc = __ldg(bo2 + jo);
#pragma unroll
            for (int i2 = 0; i2 < 16; i2++)
                acc = fmaf(so[k * 32 + i2], __ldg(Wo2 + jo * 16 + i2), acc);
            out[(size_t)gb * 3 + jo] = acc;
        }
    }
}

extern "C" void kernel_launch(void* const* d_in, const int* in_sizes, int n_in,
                              void* d_out, int out_size) {
    const float* X     = (const float*)d_in[0];
    const float* Winit = (const float*)d_in[1];
    const float* binit = (const float*)d_in[2];
    const float* Wf1   = (const float*)d_in[3];
    const float* bf1   = (const float*)d_in[4];
    const float* Wf2   = (const float*)d_in[5];
    const float* bf2   = (const float*)d_in[6];
    const float* Wo1   = (const float*)d_in[7];
    const float* bo1   = (const float*)d_in[8];
    const float* Wo2   = (const float*)d_in[9];
    const float* bo2   = (const float*)d_in[10];
    float* out = (float*)d_out;

    // 293 CTAs x 128 thr: 2 pairs/CTA x 7 batches = 4102 slots >= 4096 (tail guarded)
    cde_kernel<<<NCTA, 128>>>(X, Winit, binit, Wf1, bf1, Wf2, bf2,
                              Wo1, bo1, Wo2, bo2, out);
}